// round 11
// baseline (speedup 1.0000x reference)
#include <cuda_runtime.h>
#include <cstdint>

// ============================================================================
//   out[b, f*32+e] = sum_h relu(x[b,f]*w1[f,h]+b1[f,h]) * w2[f,h,e] + b2[f,e]
//
// Piecewise-linear reformulation: for fixed f, out = x*Sw(rank)[e]+Sb(rank)[e],
// rank = #breakpoints below x. Precompute sorted breakpoints + prefix tables;
// main kernel = batched binary searches + table FMA, 4 rows per warp-step via
// LDS.128 / STG.128, (x,rank) distributed through per-warp smem staging.
// ============================================================================
#define B_TOT 16384
#define F_TOT 128
#define H_DIM 128
#define E_DIM 32

static constexpr int ROWS_PER_CTA = 2048;
static constexpr int MAIN_GRID    = F_TOT * (B_TOT / ROWS_PER_CTA);  // 1024
static constexpr int TSTR         = 34;   // tab row stride in float2

// ---- device scratch (static allocation allowed) ----
__device__ float2 g_table[F_TOT][H_DIM + 1][E_DIM];   // {Sw, Sb} per rank
__device__ float  g_thresh[F_TOT][H_DIM];             // sorted breakpoints
__device__ float  g_xT[F_TOT][B_TOT];                 // x transposed

// ============================================================================
// Kernel 0: transpose x [B,F] -> xT [F,B]
// ============================================================================
__global__ void __launch_bounds__(256)
transpose_kernel(const float* __restrict__ x)
{
    __shared__ float tile[32][33];
    const int tx = threadIdx.x, ty = threadIdx.y;       // 32 x 8
    const int b0 = blockIdx.x * 32;
    const int f0 = blockIdx.y * 32;
    #pragma unroll
    for (int i = 0; i < 32; i += 8)
        tile[ty + i][tx] = x[(size_t)(b0 + ty + i) * F_TOT + f0 + tx];
    __syncthreads();
    #pragma unroll
    for (int i = 0; i < 32; i += 8)
        g_xT[f0 + ty + i][b0 + tx] = tile[tx][ty + i];
}

// ============================================================================
// Kernel 1: per-feature breakpoint sort + prefix tables (one CTA per feature)
// ============================================================================
__global__ void __launch_bounds__(128)
precompute_kernel(const float* __restrict__ w1, const float* __restrict__ b1,
                  const float* __restrict__ w2, const float* __restrict__ b2)
{
    const int f = blockIdx.x;
    const int tid = threadIdx.x;   // 128

    __shared__ float tS[H_DIM];
    __shared__ int   hS[H_DIM];
    __shared__ float w1s[H_DIM], b1s[H_DIM];
    __shared__ float w2s[H_DIM][E_DIM];

    const float wv = w1[f * H_DIM + tid];
    const float bv = b1[f * H_DIM + tid];
    w1s[tid] = wv;
    b1s[tid] = bv;
    tS[tid] = (wv != 0.0f) ? (-bv / wv) : __int_as_float(0x7f800000);
    hS[tid] = tid;

    for (int i = tid; i < H_DIM * E_DIM; i += 128)
        w2s[i >> 5][i & 31] = w2[(size_t)f * (H_DIM * E_DIM) + i];
    __syncthreads();

    // bitonic sort (ascending) on (tS, hS)
    for (int k = 2; k <= H_DIM; k <<= 1) {
        for (int j = k >> 1; j > 0; j >>= 1) {
            const int ix = tid ^ j;
            if (ix > tid) {
                const bool up = ((tid & k) == 0);
                const float a = tS[tid], c = tS[ix];
                if ((a > c) == up) {
                    tS[tid] = c; tS[ix] = a;
                    const int hh = hS[tid]; hS[tid] = hS[ix]; hS[ix] = hh;
                }
            }
            __syncthreads();
        }
    }

    g_thresh[f][tid] = tS[tid];

    // prefix tables: threads 0..63 -> (component, e); sequential over ranks
    if (tid < 64) {
        const int  e   = tid & 31;
        const bool isB = tid >= 32;
        float s = 0.0f;
        for (int h = 0; h < H_DIM; h++) {
            const float w = w1s[h], b = b1s[h], w2v = w2s[h][e];
            if (w < 0.0f)                          s += (isB ? b : w) * w2v;
            else if (w == 0.0f && b > 0.0f && isB) s += b * w2v;
        }
        if (isB) s += b2[f * E_DIM + e];
        if (isB) g_table[f][0][e].y = s; else g_table[f][0][e].x = s;

        for (int r = 0; r < H_DIM; r++) {
            const int   h = hS[r];
            const float w = w1s[h];
            const float sign = (w > 0.0f) ? 1.0f : ((w < 0.0f) ? -1.0f : 0.0f);
            s += sign * (isB ? b1s[h] : w) * w2s[h][e];
            if (isB) g_table[f][r + 1][e].y = s; else g_table[f][r + 1][e].x = s;
        }
    }
}

// ============================================================================
// Kernel 2: main — batched searches (4-way ILP), then sync-free store phases
// ============================================================================
__global__ void __launch_bounds__(256)
main_kernel(float* __restrict__ out)
{
    __shared__ float2 tab[(H_DIM + 1) * TSTR];   // ~35 KB padded
    __shared__ float  th[H_DIM];
    __shared__ float2 stage[8][4][32];           // per-warp, per-subiter (x, rank)

    const int tid  = threadIdx.x;
    const int lane = tid & 31;
    const int warp = tid >> 5;
    const int f    = blockIdx.x >> 3;     // 8 row-groups per feature
    const int rg   = blockIdx.x & 7;

    const float2* gt = &g_table[f][0][0];
    for (int i = tid; i < (H_DIM + 1) * E_DIM; i += 256)
        tab[(i >> 5) * TSTR + (i & 31)] = gt[i];
    if (tid < H_DIM) th[tid] = g_thresh[f][tid];
    __syncthreads();

    const float* xcol = g_xT[f];
    const int row_cta = rg * ROWS_PER_CTA;

    const int rq = lane >> 3;   // row within quad
    const int e4 = lane & 7;    // float4 slot within the 32-wide embed row

    for (int g = 0; g < 2; g++) {                 // 2 groups x 4 iters
        const int it0 = g * 4;

        // ---- phase A: 4 coalesced loads + 4 independent searches (ILP) ----
        float xvv[4];
        int   rr[4];
        #pragma unroll
        for (int ii = 0; ii < 4; ii++) {
            const int row0 = row_cta + (it0 + ii) * 256 + warp * 32;
            xvv[ii] = __ldcs(&xcol[row0 + lane]);
        }
        #pragma unroll
        for (int ii = 0; ii < 4; ii++) {
            int r = 0;
            #pragma unroll
            for (int s = 64; s; s >>= 1)
                if (xvv[ii] > th[r + s - 1]) r += s;
            if (r == 127 && xvv[ii] > th[127]) r = 128;
            rr[ii] = r;
        }

        __syncwarp();                             // prev group's reads done
        #pragma unroll
        for (int ii = 0; ii < 4; ii++)
            stage[warp][ii][lane] = make_float2(xvv[ii], __int_as_float(rr[ii]));
        __syncwarp();                             // publish

        // ---- phase B: 4 store phases, no syncs ----
        #pragma unroll
        for (int ii = 0; ii < 4; ii++) {
            const int row0 = row_cta + (it0 + ii) * 256 + warp * 32;
            float* obase = out + (size_t)(row0 + rq) * (F_TOT * E_DIM)
                               + f * E_DIM + e4 * 4;
            const float2* st = &stage[warp][ii][0];

            #pragma unroll
            for (int j = 0; j < 8; j++) {         // 4 rows per step
                const float2 pr = st[j * 4 + rq]; // broadcast LDS.64
                const float xj  = pr.x;
                const int   rj  = __float_as_int(pr.y);
                const float2* trow = &tab[rj * TSTR + e4 * 4];
                const float4 p0 = *reinterpret_cast<const float4*>(trow);
                const float4 p1 = *reinterpret_cast<const float4*>(trow + 2);
                float4 o;
                o.x = fmaf(xj, p0.x, p0.y);
                o.y = fmaf(xj, p0.z, p0.w);
                o.z = fmaf(xj, p1.x, p1.y);
                o.w = fmaf(xj, p1.z, p1.w);
                __stcs(reinterpret_cast<float4*>(
                           obase + (size_t)(j * 4) * (F_TOT * E_DIM)), o);
            }
        }
    }
}

// ============================================================================
// kernel_launch
// ============================================================================
extern "C" void kernel_launch(void* const* d_in, const int* in_sizes, int n_in,
                              void* d_out, int out_size) {
    const float* x  = (const float*)d_in[0];  // [B, F]
    const float* w1 = (const float*)d_in[1];  // [F, H]
    const float* b1 = (const float*)d_in[2];  // [F, H]
    const float* w2 = (const float*)d_in[3];  // [F, H, E]
    const float* b2 = (const float*)d_in[4];  // [F, E]
    float* out = (float*)d_out;               // [B, F*E]

    transpose_kernel<<<dim3(B_TOT / 32, F_TOT / 32), dim3(32, 8)>>>(x);
    precompute_kernel<<<F_TOT, 128>>>(w1, b1, w2, b2);
    main_kernel<<<MAIN_GRID, 256>>>(out);
}

// round 12
// speedup vs baseline: 1.4752x; 1.4752x over previous
#include <cuda_runtime.h>
#include <cstdint>

// ============================================================================
//   out[b, f*32+e] = sum_h relu(x[b,f]*w1[f,h]+b1[f,h]) * w2[f,h,e] + b2[f,e]
//
// Piecewise-linear reformulation: for fixed f, out = x*Sw(rank)[e]+Sb(rank)[e],
// rank = #breakpoints below x. Precompute sorted breakpoints + prefix tables;
// main kernel = paired binary searches (2-way ILP) + table FMA, 4 rows per
// warp-step via LDS.128 / STG.128, (x,rank) packed into 32-bit smem staging.
// ============================================================================
#define B_TOT 16384
#define F_TOT 128
#define H_DIM 128
#define E_DIM 32

static constexpr int ROWS_PER_CTA = 1024;                            // R9 geometry
static constexpr int MAIN_GRID    = F_TOT * (B_TOT / ROWS_PER_CTA);  // 2048
static constexpr int TSTR         = 34;   // tab row stride in float2

// ---- device scratch (static allocation allowed) ----
__device__ float2 g_table[F_TOT][H_DIM + 1][E_DIM];   // {Sw, Sb} per rank
__device__ float  g_thresh[F_TOT][H_DIM];             // sorted breakpoints
__device__ float  g_xT[F_TOT][B_TOT];                 // x transposed

// ============================================================================
// Kernel 0: transpose x [B,F] -> xT [F,B]
// ============================================================================
__global__ void __launch_bounds__(256)
transpose_kernel(const float* __restrict__ x)
{
    __shared__ float tile[32][33];
    const int tx = threadIdx.x, ty = threadIdx.y;       // 32 x 8
    const int b0 = blockIdx.x * 32;
    const int f0 = blockIdx.y * 32;
    #pragma unroll
    for (int i = 0; i < 32; i += 8)
        tile[ty + i][tx] = x[(size_t)(b0 + ty + i) * F_TOT + f0 + tx];
    __syncthreads();
    #pragma unroll
    for (int i = 0; i < 32; i += 8)
        g_xT[f0 + ty + i][b0 + tx] = tile[tx][ty + i];
}

// ============================================================================
// Kernel 1: per-feature breakpoint sort + prefix tables (one CTA per feature)
// ============================================================================
__global__ void __launch_bounds__(128)
precompute_kernel(const float* __restrict__ w1, const float* __restrict__ b1,
                  const float* __restrict__ w2, const float* __restrict__ b2)
{
    const int f = blockIdx.x;
    const int tid = threadIdx.x;   // 128

    __shared__ float tS[H_DIM];
    __shared__ int   hS[H_DIM];
    __shared__ float w1s[H_DIM], b1s[H_DIM];
    __shared__ float w2s[H_DIM][E_DIM];

    const float wv = w1[f * H_DIM + tid];
    const float bv = b1[f * H_DIM + tid];
    w1s[tid] = wv;
    b1s[tid] = bv;
    tS[tid] = (wv != 0.0f) ? (-bv / wv) : __int_as_float(0x7f800000);
    hS[tid] = tid;

    for (int i = tid; i < H_DIM * E_DIM; i += 128)
        w2s[i >> 5][i & 31] = w2[(size_t)f * (H_DIM * E_DIM) + i];
    __syncthreads();

    // bitonic sort (ascending) on (tS, hS)
    for (int k = 2; k <= H_DIM; k <<= 1) {
        for (int j = k >> 1; j > 0; j >>= 1) {
            const int ix = tid ^ j;
            if (ix > tid) {
                const bool up = ((tid & k) == 0);
                const float a = tS[tid], c = tS[ix];
                if ((a > c) == up) {
                    tS[tid] = c; tS[ix] = a;
                    const int hh = hS[tid]; hS[tid] = hS[ix]; hS[ix] = hh;
                }
            }
            __syncthreads();
        }
    }

    g_thresh[f][tid] = tS[tid];

    // prefix tables: threads 0..63 -> (component, e); sequential over ranks
    if (tid < 64) {
        const int  e   = tid & 31;
        const bool isB = tid >= 32;
        float s = 0.0f;
        for (int h = 0; h < H_DIM; h++) {
            const float w = w1s[h], b = b1s[h], w2v = w2s[h][e];
            if (w < 0.0f)                          s += (isB ? b : w) * w2v;
            else if (w == 0.0f && b > 0.0f && isB) s += b * w2v;
        }
        if (isB) s += b2[f * E_DIM + e];
        if (isB) g_table[f][0][e].y = s; else g_table[f][0][e].x = s;

        for (int r = 0; r < H_DIM; r++) {
            const int   h = hS[r];
            const float w = w1s[h];
            const float sign = (w > 0.0f) ? 1.0f : ((w < 0.0f) ? -1.0f : 0.0f);
            s += sign * (isB ? b1s[h] : w) * w2s[h][e];
            if (isB) g_table[f][r + 1][e].y = s; else g_table[f][r + 1][e].x = s;
        }
    }
}

// ============================================================================
// Kernel 2: main — R9 geometry, 2-iter groups, packed (x|rank) staging
// ============================================================================
__global__ void __launch_bounds__(256)
main_kernel(float* __restrict__ out)
{
    __shared__ float2   tab[(H_DIM + 1) * TSTR];   // ~34.3 KB padded
    __shared__ float    th[H_DIM];
    __shared__ uint32_t stage[8][2][32];           // packed (x & ~0xFF) | rank

    const int tid  = threadIdx.x;
    const int lane = tid & 31;
    const int warp = tid >> 5;
    const int f    = blockIdx.x >> 4;     // 16 row-groups per feature
    const int rg   = blockIdx.x & 15;

    const float2* gt = &g_table[f][0][0];
    for (int i = tid; i < (H_DIM + 1) * E_DIM; i += 256)
        tab[(i >> 5) * TSTR + (i & 31)] = gt[i];
    if (tid < H_DIM) th[tid] = g_thresh[f][tid];
    __syncthreads();

    const float* xcol = g_xT[f];
    const int row_cta = rg * ROWS_PER_CTA;

    const int rq = lane >> 3;   // row within quad
    const int e4 = lane & 7;    // float4 slot within the 32-wide embed row

    for (int g = 0; g < 2; g++) {                 // 2 groups x 2 iters
        // ---- phase A: 2 coalesced loads + 2 independent searches (ILP) ----
        float xvv[2];
        int   rr[2];
        #pragma unroll
        for (int ii = 0; ii < 2; ii++) {
            const int row0 = row_cta + ((g * 2 + ii) * 8 + warp) * 32;
            xvv[ii] = __ldcs(&xcol[row0 + lane]);
        }
        #pragma unroll
        for (int ii = 0; ii < 2; ii++) {
            int r = 0;
            #pragma unroll
            for (int s = 64; s; s >>= 1)
                if (xvv[ii] > th[r + s - 1]) r += s;
            if (r == 127 && xvv[ii] > th[127]) r = 128;
            rr[ii] = r;
        }

        __syncwarp();                             // prev group's stage reads done
        #pragma unroll
        for (int ii = 0; ii < 2; ii++)
            stage[warp][ii][lane] =
                (__float_as_uint(xvv[ii]) & 0xFFFFFF00u) | (uint32_t)rr[ii];
        __syncwarp();                             // publish

        // ---- phase B: 2 store phases, no syncs inside ----
        #pragma unroll
        for (int ii = 0; ii < 2; ii++) {
            const int row0 = row_cta + ((g * 2 + ii) * 8 + warp) * 32;
            float* obase = out + (size_t)(row0 + rq) * (F_TOT * E_DIM)
                               + f * E_DIM + e4 * 4;
            const uint32_t* st = &stage[warp][ii][0];

            #pragma unroll
            for (int j = 0; j < 8; j++) {         // 4 rows per step
                const uint32_t pk = st[j * 4 + rq];        // broadcast LDS.32
                const int   rj = (int)(pk & 0xFFu);
                const float xj = __uint_as_float(pk & 0xFFFFFF00u);
                const float2* trow = &tab[rj * TSTR + e4 * 4];
                const float4 p0 = *reinterpret_cast<const float4*>(trow);
                const float4 p1 = *reinterpret_cast<const float4*>(trow + 2);
                float4 o;
                o.x = fmaf(xj, p0.x, p0.y);
                o.y = fmaf(xj, p0.z, p0.w);
                o.z = fmaf(xj, p1.x, p1.y);
                o.w = fmaf(xj, p1.z, p1.w);
                __stcs(reinterpret_cast<float4*>(
                           obase + (size_t)(j * 4) * (F_TOT * E_DIM)), o);
            }
        }
    }
}

// ============================================================================
// kernel_launch
// ============================================================================
extern "C" void kernel_launch(void* const* d_in, const int* in_sizes, int n_in,
                              void* d_out, int out_size) {
    const float* x  = (const float*)d_in[0];  // [B, F]
    const float* w1 = (const float*)d_in[1];  // [F, H]
    const float* b1 = (const float*)d_in[2];  // [F, H]
    const float* w2 = (const float*)d_in[3];  // [F, H, E]
    const float* b2 = (const float*)d_in[4];  // [F, E]
    float* out = (float*)d_out;               // [B, F*E]

    transpose_kernel<<<dim3(B_TOT / 32, F_TOT / 32), dim3(32, 8)>>>(x);
    precompute_kernel<<<F_TOT, 128>>>(w1, b1, w2, b2);
    main_kernel<<<MAIN_GRID, 256>>>(out);
}

// round 13
// speedup vs baseline: 1.5575x; 1.0557x over previous
#include <cuda_runtime.h>
#include <cstdint>

// ============================================================================
//   out[b, f*32+e] = sum_h relu(x[b,f]*w1[f,h]+b1[f,h]) * w2[f,h,e] + b2[f,e]
//
// Piecewise-linear reformulation: for fixed f, out = x*Sw(rank)[e]+Sb(rank)[e],
// rank = #breakpoints below x. One fused prep kernel (transpose + per-feature
// sort/prefix tables), then a persistent single-wave main kernel: binary
// search + table FMA, 4 rows per warp-step via LDS.128 / STG.128.
// ============================================================================
#define B_TOT 16384
#define F_TOT 128
#define H_DIM 128
#define E_DIM 32

static constexpr int ROWS_PER_ITEM = 512;
static constexpr int N_ITEMS  = F_TOT * (B_TOT / ROWS_PER_ITEM);  // 4096
static constexpr int TSTR     = 34;   // tab row stride in float2 (conflict-light)

// ---- device scratch (static allocation allowed) ----
__device__ float2 g_table[F_TOT][H_DIM + 1][E_DIM];   // {Sw, Sb} per rank
__device__ float  g_thresh[F_TOT][H_DIM];             // sorted breakpoints
__device__ float  g_xT[F_TOT][B_TOT];                 // x transposed

// ============================================================================
// Kernel 1: fused prep.
//   CTAs [0, 2048): transpose x [B,F] -> xT [F,B] (32x32 tiles)
//   CTAs [2048, 2176): per-feature breakpoint sort + prefix tables
// ============================================================================
__global__ void __launch_bounds__(256)
prep_kernel(const float* __restrict__ x,
            const float* __restrict__ w1, const float* __restrict__ b1,
            const float* __restrict__ w2, const float* __restrict__ b2)
{
    const int c   = blockIdx.x;
    const int tid = threadIdx.x;

    if (c < 2048) {
        // ---------------- transpose part ----------------
        __shared__ float tile[32][33];
        const int tx = tid & 31, ty = tid >> 5;         // 32 x 8
        const int b0 = (c & 511) * 32;
        const int f0 = (c >> 9) * 32;
        #pragma unroll
        for (int i = 0; i < 32; i += 8)
            tile[ty + i][tx] = x[(size_t)(b0 + ty + i) * F_TOT + f0 + tx];
        __syncthreads();
        #pragma unroll
        for (int i = 0; i < 32; i += 8)
            g_xT[f0 + ty + i][b0 + tx] = tile[tx][ty + i];
        return;
    }

    // ---------------- precompute part (one CTA per feature) ----------------
    const int f = c - 2048;

    __shared__ float tS[H_DIM];
    __shared__ int   hS[H_DIM];
    __shared__ float w1s[H_DIM], b1s[H_DIM];
    __shared__ float w2s[H_DIM][E_DIM];

    if (tid < H_DIM) {
        const float wv = w1[f * H_DIM + tid];
        const float bv = b1[f * H_DIM + tid];
        w1s[tid] = wv;
        b1s[tid] = bv;
        tS[tid] = (wv != 0.0f) ? (-bv / wv) : __int_as_float(0x7f800000);
        hS[tid] = tid;
    }
    for (int i = tid; i < H_DIM * E_DIM; i += 256)
        w2s[i >> 5][i & 31] = w2[(size_t)f * (H_DIM * E_DIM) + i];
    __syncthreads();

    // bitonic sort (ascending) on (tS, hS), 128 elems; barriers CTA-wide
    for (int k = 2; k <= H_DIM; k <<= 1) {
        for (int j = k >> 1; j > 0; j >>= 1) {
            if (tid < H_DIM) {
                const int ix = tid ^ j;
                if (ix > tid) {
                    const bool up = ((tid & k) == 0);
                    const float a = tS[tid], cc = tS[ix];
                    if ((a > cc) == up) {
                        tS[tid] = cc; tS[ix] = a;
                        const int hh = hS[tid]; hS[tid] = hS[ix]; hS[ix] = hh;
                    }
                }
            }
            __syncthreads();
        }
    }

    if (tid < H_DIM) g_thresh[f][tid] = tS[tid];

    // prefix tables: threads 0..63 -> (component, e); sequential over ranks
    if (tid < 64) {
        const int  e   = tid & 31;
        const bool isB = tid >= 32;
        float s = 0.0f;
        for (int h = 0; h < H_DIM; h++) {
            const float w = w1s[h], b = b1s[h], w2v = w2s[h][e];
            if (w < 0.0f)                          s += (isB ? b : w) * w2v;
            else if (w == 0.0f && b > 0.0f && isB) s += b * w2v;
        }
        if (isB) s += b2[f * E_DIM + e];
        if (isB) g_table[f][0][e].y = s; else g_table[f][0][e].x = s;

        for (int r = 0; r < H_DIM; r++) {
            const int   h = hS[r];
            const float w = w1s[h];
            const float sign = (w > 0.0f) ? 1.0f : ((w < 0.0f) ? -1.0f : 0.0f);
            s += sign * (isB ? b1s[h] : w) * w2s[h][e];
            if (isB) g_table[f][r + 1][e].y = s; else g_table[f][r + 1][e].x = s;
        }
    }
}

// ============================================================================
// Kernel 2: main — persistent single-wave CTAs over f-major work items.
//   Table reloaded only on f-change. Inner machinery = validated R12 path.
// ============================================================================
__global__ void __launch_bounds__(256)
main_kernel(float* __restrict__ out, int base, int rem)
{
    __shared__ float2   tab[(H_DIM + 1) * TSTR];   // ~34.3 KB padded
    __shared__ float    th[H_DIM];
    __shared__ uint32_t stage[8][2][32];           // packed (x & ~0xFF) | rank

    const int tid  = threadIdx.x;
    const int lane = tid & 31;
    const int warp = tid >> 5;
    const int c    = blockIdx.x;

    // contiguous run of items for this CTA
    const int cnt   = base + (c < rem ? 1 : 0);
    const int start = c * base + (c < rem ? c : rem);

    const int rq = lane >> 3;   // row within quad
    const int e4 = lane & 7;    // float4 slot within the 32-wide embed row

    int f_cur = -1;

    for (int w = 0; w < cnt; w++) {
        const int item = start + w;
        const int f    = item >> 5;           // 32 row-groups per feature
        const int rg   = item & 31;

        if (f != f_cur) {
            __syncthreads();                  // old table fully consumed
            const float2* gt = &g_table[f][0][0];
            for (int i = tid; i < (H_DIM + 1) * E_DIM; i += 256)
                tab[(i >> 5) * TSTR + (i & 31)] = gt[i];
            if (tid < H_DIM) th[tid] = g_thresh[f][tid];
            __syncthreads();
            f_cur = f;
        }

        const float* xcol = g_xT[f];
        const int row_item = rg * ROWS_PER_ITEM;

        // ---- phase A: 2 coalesced loads + 2 independent searches ----
        float xvv[2];
        int   rr[2];
        #pragma unroll
        for (int ii = 0; ii < 2; ii++) {
            const int row0 = row_item + ii * 256 + warp * 32;
            xvv[ii] = __ldcs(&xcol[row0 + lane]);
        }
        #pragma unroll
        for (int ii = 0; ii < 2; ii++) {
            int r = 0;
            #pragma unroll
            for (int s = 64; s; s >>= 1)
                if (xvv[ii] > th[r + s - 1]) r += s;
            if (r == 127 && xvv[ii] > th[127]) r = 128;
            rr[ii] = r;
        }

        __syncwarp();                         // prev item's stage reads done
        #pragma unroll
        for (int ii = 0; ii < 2; ii++)
            stage[warp][ii][lane] =
                (__float_as_uint(xvv[ii]) & 0xFFFFFF00u) | (uint32_t)rr[ii];
        __syncwarp();                         // publish

        // ---- phase B: 2 store phases, no syncs inside ----
        #pragma unroll
        for (int ii = 0; ii < 2; ii++) {
            const int row0 = row_item + ii * 256 + warp * 32;
            float* obase = out + (size_t)(row0 + rq) * (F_TOT * E_DIM)
                               + f * E_DIM + e4 * 4;
            const uint32_t* st = &stage[warp][ii][0];

            #pragma unroll
            for (int j = 0; j < 8; j++) {     // 4 rows per step
                const uint32_t pk = st[j * 4 + rq];      // broadcast LDS.32
                const int   rj = (int)(pk & 0xFFu);
                const float xj = __uint_as_float(pk & 0xFFFFFF00u);
                const float2* trow = &tab[rj * TSTR + e4 * 4];
                const float4 p0 = *reinterpret_cast<const float4*>(trow);
                const float4 p1 = *reinterpret_cast<const float4*>(trow + 2);
                float4 o;
                o.x = fmaf(xj, p0.x, p0.y);
                o.y = fmaf(xj, p0.z, p0.w);
                o.z = fmaf(xj, p1.x, p1.y);
                o.w = fmaf(xj, p1.z, p1.w);
                __stcs(reinterpret_cast<float4*>(
                           obase + (size_t)(j * 4) * (F_TOT * E_DIM)), o);
            }
        }
    }
}

// ============================================================================
// kernel_launch
// ============================================================================
extern "C" void kernel_launch(void* const* d_in, const int* in_sizes, int n_in,
                              void* d_out, int out_size) {
    const float* x  = (const float*)d_in[0];  // [B, F]
    const float* w1 = (const float*)d_in[1];  // [F, H]
    const float* b1 = (const float*)d_in[2];  // [F, H]
    const float* w2 = (const float*)d_in[3];  // [F, H, E]
    const float* b2 = (const float*)d_in[4];  // [F, E]
    float* out = (float*)d_out;               // [B, F*E]

    int sms = 148;
    cudaDeviceGetAttribute(&sms, cudaDevAttrMultiProcessorCount, 0);
    const int G    = sms * 6;                 // single wave at 6 CTAs/SM
    const int base = N_ITEMS / G;
    const int rem  = N_ITEMS % G;

    prep_kernel<<<2048 + F_TOT, 256>>>(x, w1, b1, w2, b2);
    main_kernel<<<G, 256>>>(out, base, rem);
}

// round 14
// speedup vs baseline: 1.7871x; 1.1474x over previous
#include <cuda_runtime.h>
#include <cstdint>

// ============================================================================
//   out[b, f*32+e] = sum_h relu(x[b,f]*w1[f,h]+b1[f,h]) * w2[f,h,e] + b2[f,e]
//
// Piecewise-linear reformulation: for fixed f, out = x*Sw(rank)[e]+Sb(rank)[e],
// rank = #breakpoints below x. Fused prep (transpose + per-feature tables via
// parallel deltas), then persistent single-wave main kernel: binary search +
// per-row conflict-free LDS.64 table read + STG.32.
// ============================================================================
#define B_TOT 16384
#define F_TOT 128
#define H_DIM 128
#define E_DIM 32

static constexpr int ROWS_PER_ITEM = 512;
static constexpr int N_ITEMS  = F_TOT * (B_TOT / ROWS_PER_ITEM);  // 4096
static constexpr int TSTR     = 33;   // tab row stride in float2

// ---- device scratch (static allocation allowed) ----
__device__ float2 g_table[F_TOT][H_DIM + 1][E_DIM];   // {Sw, Sb} per rank
__device__ float  g_thresh[F_TOT][H_DIM];             // sorted breakpoints
__device__ float  g_xT[F_TOT][B_TOT];                 // x transposed

// ============================================================================
// Kernel 1: fused prep.
//   CTAs [0, 2048): transpose x [B,F] -> xT [F,B] (32x32 tiles)
//   CTAs [2048, 2176): per-feature breakpoint sort + prefix tables
// ============================================================================
__global__ void __launch_bounds__(256)
prep_kernel(const float* __restrict__ x,
            const float* __restrict__ w1, const float* __restrict__ b1,
            const float* __restrict__ w2, const float* __restrict__ b2)
{
    const int c   = blockIdx.x;
    const int tid = threadIdx.x;

    if (c < 2048) {
        // ---------------- transpose part ----------------
        __shared__ float tile[32][33];
        const int tx = tid & 31, ty = tid >> 5;         // 32 x 8
        const int b0 = (c & 511) * 32;
        const int f0 = (c >> 9) * 32;
        #pragma unroll
        for (int i = 0; i < 32; i += 8)
            tile[ty + i][tx] = x[(size_t)(b0 + ty + i) * F_TOT + f0 + tx];
        __syncthreads();
        #pragma unroll
        for (int i = 0; i < 32; i += 8)
            g_xT[f0 + ty + i][b0 + tx] = tile[tx][ty + i];
        return;
    }

    // ---------------- precompute part (one CTA per feature) ----------------
    const int f = c - 2048;
    const float* w2f = w2 + (size_t)f * (H_DIM * E_DIM);

    __shared__ float2 dlt[H_DIM][E_DIM];      // per-rank {dW, dB} deltas, 32 KB
    __shared__ float2 bpart[8][E_DIM];        // base partial sums
    __shared__ float  tS[H_DIM];
    __shared__ int    hS[H_DIM];
    __shared__ float  w1s[H_DIM], b1s[H_DIM];

    if (tid < H_DIM) {
        const float wv = w1[f * H_DIM + tid];
        const float bv = b1[f * H_DIM + tid];
        w1s[tid] = wv;
        b1s[tid] = bv;
        tS[tid] = (wv != 0.0f) ? (-bv / wv) : __int_as_float(0x7f800000);
        hS[tid] = tid;
    }
    __syncthreads();

    // bitonic sort (ascending) on (tS, hS), 128 elems; barriers CTA-wide
    for (int k = 2; k <= H_DIM; k <<= 1) {
        for (int j = k >> 1; j > 0; j >>= 1) {
            if (tid < H_DIM) {
                const int ix = tid ^ j;
                if (ix > tid) {
                    const bool up = ((tid & k) == 0);
                    const float a = tS[tid], cc = tS[ix];
                    if ((a > cc) == up) {
                        tS[tid] = cc; tS[ix] = a;
                        const int hh = hS[tid]; hS[tid] = hS[ix]; hS[ix] = hh;
                    }
                }
            }
            __syncthreads();
        }
    }

    if (tid < H_DIM) g_thresh[f][tid] = tS[tid];

    // parallel per-rank deltas: crossing rank r upward toggles unit hS[r]
    for (int i = tid; i < H_DIM * E_DIM; i += 256) {
        const int r = i >> 5, e = i & 31;
        const int h = hS[r];
        const float w = w1s[h];
        const float sign = (w > 0.0f) ? 1.0f : ((w < 0.0f) ? -1.0f : 0.0f);
        const float w2v = w2f[h * E_DIM + e];
        dlt[r][e] = make_float2(sign * w * w2v, sign * b1s[h] * w2v);
    }

    // parallel base state at x = -inf (8 partials x 32 e)
    {
        const int e = tid & 31, part = tid >> 5;
        float sW = 0.0f, sB = 0.0f;
        for (int h = part * 16; h < part * 16 + 16; h++) {
            const float w = w1s[h], b = b1s[h];
            const float w2v = w2f[h * E_DIM + e];
            if (w < 0.0f)                 { sW += w * w2v; sB += b * w2v; }
            else if (w == 0.0f && b > 0.0f) sB += b * w2v;
        }
        bpart[part][e] = make_float2(sW, sB);
    }
    __syncthreads();

    // sequential accumulation over ranks (cheap now: LDS.64 + FFMA per step)
    if (tid < E_DIM) {
        const int e = tid;
        float sW = 0.0f, sB = b2[f * E_DIM + e];
        #pragma unroll
        for (int p = 0; p < 8; p++) { sW += bpart[p][e].x; sB += bpart[p][e].y; }
        g_table[f][0][e] = make_float2(sW, sB);
        for (int r = 0; r < H_DIM; r++) {
            const float2 d = dlt[r][e];
            sW += d.x; sB += d.y;
            g_table[f][r + 1][e] = make_float2(sW, sB);
        }
    }
}

// ============================================================================
// Kernel 2: main — persistent single-wave CTAs over f-major work items.
//   Store phase: one row per step, lane e reads tab[rank][e] as float2
//   (256 B linear LDS.64, conflict-free) then STG.32 (128 B coalesced).
// ============================================================================
__global__ void __launch_bounds__(256)
main_kernel(float* __restrict__ out, int base, int rem)
{
    __shared__ float2   tab[(H_DIM + 1) * TSTR];   // ~33.3 KB
    __shared__ float    th[H_DIM];
    __shared__ uint32_t stage[8][2][32];           // packed (x & ~0xFF) | rank

    const int tid  = threadIdx.x;
    const int lane = tid & 31;
    const int warp = tid >> 5;
    const int c    = blockIdx.x;

    // contiguous run of items for this CTA
    const int cnt   = base + (c < rem ? 1 : 0);
    const int start = c * base + (c < rem ? c : rem);

    int f_cur = -1;

    for (int w = 0; w < cnt; w++) {
        const int item = start + w;
        const int f    = item >> 5;           // 32 row-groups per feature
        const int rg   = item & 31;

        if (f != f_cur) {
            __syncthreads();                  // old table fully consumed
            const float2* gt = &g_table[f][0][0];
            for (int i = tid; i < (H_DIM + 1) * E_DIM; i += 256)
                tab[(i >> 5) * TSTR + (i & 31)] = gt[i];
            if (tid < H_DIM) th[tid] = g_thresh[f][tid];
            __syncthreads();
            f_cur = f;
        }

        const float* xcol = g_xT[f];
        const int row_item = rg * ROWS_PER_ITEM;

        // ---- phase A: 2 coalesced loads + 2 independent searches ----
        float xvv[2];
        int   rr[2];
        #pragma unroll
        for (int ii = 0; ii < 2; ii++) {
            const int row0 = row_item + ii * 256 + warp * 32;
            xvv[ii] = __ldcs(&xcol[row0 + lane]);
        }
        #pragma unroll
        for (int ii = 0; ii < 2; ii++) {
            int r = 0;
            #pragma unroll
            for (int s = 64; s; s >>= 1)
                if (xvv[ii] > th[r + s - 1]) r += s;
            if (r == 127 && xvv[ii] > th[127]) r = 128;
            rr[ii] = r;
        }

        __syncwarp();                         // prev item's stage reads done
        #pragma unroll
        for (int ii = 0; ii < 2; ii++)
            stage[warp][ii][lane] =
                (__float_as_uint(xvv[ii]) & 0xFFFFFF00u) | (uint32_t)rr[ii];
        __syncwarp();                         // publish

        // ---- phase B: 2 store phases; one row per step, conflict-free ----
        #pragma unroll
        for (int ii = 0; ii < 2; ii++) {
            const int row0 = row_item + ii * 256 + warp * 32;
            float* obase = out + (size_t)row0 * (F_TOT * E_DIM)
                               + f * E_DIM + lane;
            const uint32_t* st = &stage[warp][ii][0];

            #pragma unroll
            for (int j = 0; j < 32; j++) {
                const uint32_t pk = st[j];                 // broadcast LDS.32
                const int   rj = (int)(pk & 0xFFu);
                const float xj = __uint_as_float(pk & 0xFFFFFF00u);
                const float2 sv = tab[rj * TSTR + lane];   // linear 256 B LDS.64
                __stcs(obase + (size_t)j * (F_TOT * E_DIM),
                       fmaf(xj, sv.x, sv.y));
            }
        }
    }
}

// ============================================================================
// kernel_launch
// ============================================================================
extern "C" void kernel_launch(void* const* d_in, const int* in_sizes, int n_in,
                              void* d_out, int out_size) {
    const float* x  = (const float*)d_in[0];  // [B, F]
    const float* w1 = (const float*)d_in[1];  // [F, H]
    const float* b1 = (const float*)d_in[2];  // [F, H]
    const float* w2 = (const float*)d_in[3];  // [F, H, E]
    const float* b2 = (const float*)d_in[4];  // [F, E]
    float* out = (float*)d_out;               // [B, F*E]

    int sms = 148;
    cudaDeviceGetAttribute(&sms, cudaDevAttrMultiProcessorCount, 0);
    const int G    = sms * 6;                 // single wave at 6 CTAs/SM
    const int base = N_ITEMS / G;
    const int rem  = N_ITEMS % G;

    prep_kernel<<<2048 + F_TOT, 256>>>(x, w1, b1, w2, b2);
    main_kernel<<<G, 256>>>(out, base, rem);
}

// round 16
// speedup vs baseline: 1.8811x; 1.0526x over previous
#include <cuda_runtime.h>
#include <cstdint>

// ============================================================================
//   out[b, f*32+e] = sum_h relu(x[b,f]*w1[f,h]+b1[f,h]) * w2[f,h,e] + b2[f,e]
//
// Piecewise-linear reformulation: for fixed f, out = x*Sw(rank)[e]+Sb(rank)[e],
// rank = #breakpoints below x. Fused prep (vectorized transpose + per-feature
// tables via parallel deltas), then persistent single-wave main kernel:
// binary search + pair-row float4 table reads + STG.64 stores.
// ============================================================================
#define B_TOT 16384
#define F_TOT 128
#define H_DIM 128
#define E_DIM 32

static constexpr int ROWS_PER_ITEM = 512;
static constexpr int N_ITEMS  = F_TOT * (B_TOT / ROWS_PER_ITEM);  // 4096
static constexpr int TSTR     = 34;   // tab row stride in float2 (16B-aligned)

// ---- device scratch (static allocation allowed) ----
__device__ float2 g_table[F_TOT][H_DIM + 1][E_DIM];   // {Sw, Sb} per rank
__device__ float  g_thresh[F_TOT][H_DIM];             // sorted breakpoints
__device__ float  g_xT[F_TOT][B_TOT];                 // x transposed

// ============================================================================
// Kernel 1: fused prep.
//   CTAs [0, 512): transpose x [B,F] -> xT [F,B], 32 rows x 128 f per CTA
//   CTAs [512, 640): per-feature breakpoint sort + prefix tables
// ============================================================================
__global__ void __launch_bounds__(256)
prep_kernel(const float* __restrict__ x,
            const float* __restrict__ w1, const float* __restrict__ b1,
            const float* __restrict__ w2, const float* __restrict__ b2)
{
    const int c   = blockIdx.x;
    const int tid = threadIdx.x;

    if (c < 512) {
        // ---------------- transpose part (vectorized) ----------------
        __shared__ float tile[32][129];
        const int b0 = c * 32;
        // load 32 rows x 128 f with float4 (4 rounds)
        #pragma unroll
        for (int i = 0; i < 4; i++) {
            const int flat = (i * 256 + tid) * 4;      // float index
            const int r = flat >> 7, fq = flat & 127;
            const float4 v = *reinterpret_cast<const float4*>(
                &x[(size_t)(b0 + r) * F_TOT + fq]);
            tile[r][fq]     = v.x;
            tile[r][fq + 1] = v.y;
            tile[r][fq + 2] = v.z;
            tile[r][fq + 3] = v.w;
        }
        __syncthreads();
        // store: 16 rounds, 8 warps x (f = k*8 + warp), lane = b  (128 B coalesced)
        const int lane = tid & 31, warp = tid >> 5;
        #pragma unroll
        for (int k = 0; k < 16; k++) {
            const int f = k * 8 + warp;
            g_xT[f][b0 + lane] = tile[lane][f];
        }
        return;
    }

    // ---------------- precompute part (one CTA per feature) ----------------
    const int f = c - 512;
    const float* w2f = w2 + (size_t)f * (H_DIM * E_DIM);

    __shared__ float2 dlt[H_DIM][E_DIM];      // per-rank {dW, dB} deltas, 32 KB
    __shared__ float2 bpart[8][E_DIM];        // base partial sums
    __shared__ float  tS[H_DIM];
    __shared__ int    hS[H_DIM];
    __shared__ float  w1s[H_DIM], b1s[H_DIM];

    if (tid < H_DIM) {
        const float wv = w1[f * H_DIM + tid];
        const float bv = b1[f * H_DIM + tid];
        w1s[tid] = wv;
        b1s[tid] = bv;
        tS[tid] = (wv != 0.0f) ? (-bv / wv) : __int_as_float(0x7f800000);
        hS[tid] = tid;
    }
    __syncthreads();

    // bitonic sort (ascending) on (tS, hS), 128 elems; barriers CTA-wide
    for (int k = 2; k <= H_DIM; k <<= 1) {
        for (int j = k >> 1; j > 0; j >>= 1) {
            if (tid < H_DIM) {
                const int ix = tid ^ j;
                if (ix > tid) {
                    const bool up = ((tid & k) == 0);
                    const float a = tS[tid], cc = tS[ix];
                    if ((a > cc) == up) {
                        tS[tid] = cc; tS[ix] = a;
                        const int hh = hS[tid]; hS[tid] = hS[ix]; hS[ix] = hh;
                    }
                }
            }
            __syncthreads();
        }
    }

    if (tid < H_DIM) g_thresh[f][tid] = tS[tid];

    // parallel per-rank deltas: crossing rank r upward toggles unit hS[r]
    for (int i = tid; i < H_DIM * E_DIM; i += 256) {
        const int r = i >> 5, e = i & 31;
        const int h = hS[r];
        const float w = w1s[h];
        const float sign = (w > 0.0f) ? 1.0f : ((w < 0.0f) ? -1.0f : 0.0f);
        const float w2v = w2f[h * E_DIM + e];
        dlt[r][e] = make_float2(sign * w * w2v, sign * b1s[h] * w2v);
    }

    // parallel base state at x = -inf (8 partials x 32 e)
    {
        const int e = tid & 31, part = tid >> 5;
        float sW = 0.0f, sB = 0.0f;
        for (int h = part * 16; h < part * 16 + 16; h++) {
            const float w = w1s[h], b = b1s[h];
            const float w2v = w2f[h * E_DIM + e];
            if (w < 0.0f)                 { sW += w * w2v; sB += b * w2v; }
            else if (w == 0.0f && b > 0.0f) sB += b * w2v;
        }
        bpart[part][e] = make_float2(sW, sB);
    }
    __syncthreads();

    // sequential accumulation over ranks (LDS.64 + FADD per step, 32 threads)
    if (tid < E_DIM) {
        const int e = tid;
        float sW = 0.0f, sB = b2[f * E_DIM + e];
        #pragma unroll
        for (int p = 0; p < 8; p++) { sW += bpart[p][e].x; sB += bpart[p][e].y; }
        g_table[f][0][e] = make_float2(sW, sB);
        for (int r = 0; r < H_DIM; r++) {
            const float2 d = dlt[r][e];
            sW += d.x; sB += d.y;
            g_table[f][r + 1][e] = make_float2(sW, sB);
        }
    }
}

// ============================================================================
// Kernel 2: main — persistent single-wave CTAs over f-major work items.
//   Store phase: 2 rows per step; half-warps read tab[rank][2*le] as float4
//   (linear 256 B per half) and store both rows with one STG.64 each.
// ============================================================================
__global__ void __launch_bounds__(256)
main_kernel(float* __restrict__ out, int base, int rem)
{
    __shared__ float2   tab[(H_DIM + 1) * TSTR];   // ~34.3 KB
    __shared__ float    th[H_DIM];
    __shared__ uint32_t stage[8][2][32];           // packed (x & ~0xFF) | rank

    const int tid  = threadIdx.x;
    const int lane = tid & 31;
    const int warp = tid >> 5;
    const int half = lane >> 4;   // 0/1: which row of the pair
    const int le   = lane & 15;   // float2 slot within the 32-wide embed row
    const int c    = blockIdx.x;

    // contiguous run of items for this CTA
    const int cnt   = base + (c < rem ? 1 : 0);
    const int start = c * base + (c < rem ? c : rem);

    int f_cur = -1;

    for (int w = 0; w < cnt; w++) {
        const int item = start + w;
        const int f    = item >> 5;           // 32 row-groups per feature
        const int rg   = item & 31;

        if (f != f_cur) {
            __syncthreads();                  // old table fully consumed
            const float2* gt = &g_table[f][0][0];
            for (int i = tid; i < (H_DIM + 1) * E_DIM; i += 256)
                tab[(i >> 5) * TSTR + (i & 31)] = gt[i];
            if (tid < H_DIM) th[tid] = g_thresh[f][tid];
            __syncthreads();
            f_cur = f;
        }

        const float* xcol = g_xT[f];
        const int row_item = rg * ROWS_PER_ITEM;

        // ---- phase A: 2 coalesced loads + 2 independent searches ----
        float xvv[2];
        int   rr[2];
        #pragma unroll
        for (int ii = 0; ii < 2; ii++) {
            const int row0 = row_item + ii * 256 + warp * 32;
            xvv[ii] = __ldcs(&xcol[row0 + lane]);
        }
        #pragma unroll
        for (int ii = 0; ii < 2; ii++) {
            int r = 0;
            #pragma unroll
            for (int s = 64; s; s >>= 1)
                if (xvv[ii] > th[r + s - 1]) r += s;
            if (r == 127 && xvv[ii] > th[127]) r = 128;
            rr[ii] = r;
        }

        __syncwarp();                         // prev item's stage reads done
        #pragma unroll
        for (int ii = 0; ii < 2; ii++)
            stage[warp][ii][lane] =
                (__float_as_uint(xvv[ii]) & 0xFFFFFF00u) | (uint32_t)rr[ii];
        __syncwarp();                         // publish

        // ---- phase B: 2 store phases; 2 rows per step, conflict-free ----
        #pragma unroll
        for (int ii = 0; ii < 2; ii++) {
            const int row0 = row_item + ii * 256 + warp * 32;
            float* obase = out + (size_t)(row0 + half) * (F_TOT * E_DIM)
                               + f * E_DIM + le * 2;
            const uint32_t* st = &stage[warp][ii][0];

            #pragma unroll
            for (int j = 0; j < 16; j++) {
                const uint32_t pk = st[j * 2 + half];      // broadcast LDS.32
                const int   rj = (int)(pk & 0xFFu);
                const float xj = __uint_as_float(pk & 0xFFFFFF00u);
                const float4 p = *reinterpret_cast<const float4*>(
                    &tab[rj * TSTR + le * 2]);             // linear 256 B / half
                float2 o;
                o.x = fmaf(xj, p.x, p.y);
                o.y = fmaf(xj, p.z, p.w);
                __stcs(reinterpret_cast<float2*>(
                           obase + (size_t)(j * 2) * (F_TOT * E_DIM)), o);
            }
        }
    }
}

// ============================================================================
// kernel_launch
// ============================================================================
extern "C" void kernel_launch(void* const* d_in, const int* in_sizes, int n_in,
                              void* d_out, int out_size) {
    const float* x  = (const float*)d_in[0];  // [B, F]
    const float* w1 = (const float*)d_in[1];  // [F, H]
    const float* b1 = (const float*)d_in[2];  // [F, H]
    const float* w2 = (const float*)d_in[3];  // [F, H, E]
    const float* b2 = (const float*)d_in[4];  // [F, E]
    float* out = (float*)d_out;               // [B, F*E]

    int sms = 148;
    cudaDeviceGetAttribute(&sms, cudaDevAttrMultiProcessorCount, 0);
    const int G    = sms * 6;                 // single wave at 6 CTAs/SM
    const int base = N_ITEMS / G;
    const int rem  = N_ITEMS % G;

    prep_kernel<<<512 + F_TOT, 256>>>(x, w1, b1, w2, b2);
    main_kernel<<<G, 256>>>(out, base, rem);
}